// round 1
// baseline (speedup 1.0000x reference)
#include <cuda_runtime.h>

// Problem shapes (fixed by the dataset):
//   x: [B=4, S=4096]  (values unused -- only shape matters)
//   W: [D=1024, ML=8192]
//   b: [D=1024]
//   out: [B, S, D] = W[:, :S].T + b, broadcast over B
#define B_DIM 4
#define S_DIM 4096
#define D_DIM 1024
#define ML_DIM 8192

// 32x32 transpose tile, 32x8 threads, each thread handles 4 rows.
__global__ void posemb_transpose_kernel(const float* __restrict__ W,
                                        const float* __restrict__ bias,
                                        float* __restrict__ out) {
    __shared__ float tile[32][33];  // +1 pad: conflict-free transposed reads

    const int s0 = blockIdx.x * 32;
    const int d0 = blockIdx.y * 32;
    const int x = threadIdx.x;   // 0..31
    const int y = threadIdx.y;   // 0..7

    // Coalesced load: consecutive threads read consecutive s within a W row.
#pragma unroll
    for (int k = 0; k < 4; k++) {
        const int dl = y + 8 * k;
        tile[dl][x] = W[(size_t)(d0 + dl) * ML_DIM + (s0 + x)];
    }
    __syncthreads();

    const float bv = bias[d0 + x];

    // Coalesced store: consecutive threads write consecutive d for fixed s.
#pragma unroll
    for (int k = 0; k < 4; k++) {
        const int sl = y + 8 * k;
        const float v = tile[x][sl] + bv;
        const size_t base = (size_t)(s0 + sl) * D_DIM + (d0 + x);
#pragma unroll
        for (int bb = 0; bb < B_DIM; bb++) {
            out[(size_t)bb * (S_DIM * D_DIM) + base] = v;
        }
    }
}

extern "C" void kernel_launch(void* const* d_in, const int* in_sizes, int n_in,
                              void* d_out, int out_size) {
    (void)in_sizes; (void)n_in; (void)out_size;
    const float* W    = (const float*)d_in[1];
    const float* bias = (const float*)d_in[2];
    float* out        = (float*)d_out;

    dim3 block(32, 8);
    dim3 grid(S_DIM / 32, D_DIM / 32);  // 128 x 32 = 4096 blocks
    posemb_transpose_kernel<<<grid, block>>>(W, bias, out);
}